// round 3
// baseline (speedup 1.0000x reference)
#include <cuda_runtime.h>

#define NH      12
#define DMODEL  768
#define HD      64
#define BATCH   2
#define NQ      1024
#define SK      4096
#define ATTN_SCALE 0.125f
#define NEG_BIG   -10000.0f

// Scratch (allocation-free rule: __device__ globals)
__device__ float g_Qp[BATCH * NQ * DMODEL];
__device__ float g_Kp[BATCH * SK * DMODEL];
__device__ float g_Vp[BATCH * SK * DMODEL];
__device__ float g_AO[BATCH * NQ * DMODEL];

// ---------------------------------------------------------------------------
// C[M][N] = A[M][K] @ W[N][K]^T (+ bias). 128x128x16 tile, 256 thr, 8x8/thread.
// Shared tiles k-major with chunk-XOR swizzle: (k, m) -> T[k][((m/4+k)&31)*4+m%4],
// so transposed stores AND float4 fragment reads are bank-conflict-free.
// Register-staged double buffering overlaps next tile's global loads with the
// 16-step FFMA phase.
// ---------------------------------------------------------------------------
template<bool BIAS>
__global__ __launch_bounds__(256) void gemm_xwt(
    const float* __restrict__ A, const float* __restrict__ W,
    const float* __restrict__ bias, float* __restrict__ C,
    int M, int N, int K)
{
    __shared__ float As[16][128];
    __shared__ float Bs[16][128];
    const int m0 = blockIdx.y * 128;
    const int n0 = blockIdx.x * 128;
    const int tid = threadIdx.x;
    const int tx = tid & 15;
    const int ty = tid >> 4;

    float acc[8][8];
    #pragma unroll
    for (int i = 0; i < 8; i++)
        #pragma unroll
        for (int j = 0; j < 8; j++) acc[i][j] = 0.f;

    int lm[2], lc4[2];
    #pragma unroll
    for (int it = 0; it < 2; it++) {
        int id = it * 256 + tid;
        lm[it]  = id >> 2;
        lc4[it] = id & 3;
    }

    float4 av[2], wv[2];
    #pragma unroll
    for (int it = 0; it < 2; it++) {
        av[it] = *(const float4*)(A + (m0 + lm[it]) * K + lc4[it] * 4);
        wv[it] = *(const float4*)(W + (n0 + lm[it]) * K + lc4[it] * 4);
    }

    for (int kt = 0; kt < K; kt += 16) {
        #pragma unroll
        for (int it = 0; it < 2; it++) {
            int m = lm[it];
            int mb = m >> 2, mo = m & 3;
            #pragma unroll
            for (int j = 0; j < 4; j++) {
                int k  = lc4[it] * 4 + j;
                int ch = (mb + k) & 31;
                As[k][ch * 4 + mo] = ((const float*)&av[it])[j];
                Bs[k][ch * 4 + mo] = ((const float*)&wv[it])[j];
            }
        }
        __syncthreads();

        if (kt + 16 < K) {
            #pragma unroll
            for (int it = 0; it < 2; it++) {
                av[it] = *(const float4*)(A + (m0 + lm[it]) * K + kt + 16 + lc4[it] * 4);
                wv[it] = *(const float4*)(W + (n0 + lm[it]) * K + kt + 16 + lc4[it] * 4);
            }
        }

        #pragma unroll
        for (int k = 0; k < 16; k++) {
            float a[8], b[8];
            #pragma unroll
            for (int hh = 0; hh < 2; hh++) {
                int cha = (hh * 16 + ty + k) & 31;
                float4 a4 = *(const float4*)&As[k][cha * 4];
                a[hh*4+0] = a4.x; a[hh*4+1] = a4.y; a[hh*4+2] = a4.z; a[hh*4+3] = a4.w;
                int chb = (hh * 16 + tx + k) & 31;
                float4 b4 = *(const float4*)&Bs[k][chb * 4];
                b[hh*4+0] = b4.x; b[hh*4+1] = b4.y; b[hh*4+2] = b4.z; b[hh*4+3] = b4.w;
            }
            #pragma unroll
            for (int i = 0; i < 8; i++)
                #pragma unroll
                for (int j = 0; j < 8; j++)
                    acc[i][j] += a[i] * b[j];
        }
        __syncthreads();
    }

    #pragma unroll
    for (int hi = 0; hi < 2; hi++)
        #pragma unroll
        for (int i = 0; i < 4; i++) {
            int row = m0 + hi * 64 + ty * 4 + i;
            #pragma unroll
            for (int hj = 0; hj < 2; hj++) {
                int col = n0 + hj * 64 + tx * 4;
                float4 v;
                v.x = acc[hi*4+i][hj*4+0];
                v.y = acc[hi*4+i][hj*4+1];
                v.z = acc[hi*4+i][hj*4+2];
                v.w = acc[hi*4+i][hj*4+3];
                if (BIAS) {
                    v.x += bias[col+0]; v.y += bias[col+1];
                    v.z += bias[col+2]; v.w += bias[col+3];
                }
                *(float4*)(C + row * N + col) = v;
            }
        }
}

// ---------------------------------------------------------------------------
// Flash-attention style: 64 query rows x full head per block; S in tiles of 64.
// Qs, KP d-major with mod-16 chunk swizzle; KP reused as exp(P) after scores.
// Vs: [s][swz(c)]. Softmax/PV use per-row index rotation for conflict-free reads.
// K/V (+mask) tiles are register double-buffered: next tile's global loads are
// issued right after the current tile's smem stores, overlapping the L2 stream
// with the score FFMA phase.
// Masked score = exactly -10000 and V zeroed by mask -> matches reference even
// for fully-masked rows. Static smem = 3*16KB = 48KB.
// ---------------------------------------------------------------------------
__global__ __launch_bounds__(256, 2) void attn_fwd(
    const float* __restrict__ Q, const float* __restrict__ K,
    const float* __restrict__ V, const float* __restrict__ mask,
    float* __restrict__ O)
{
    __shared__ float Qs[64][64];
    __shared__ float KP[64][64];
    __shared__ float Vs[64][64];

    const int n0 = blockIdx.x * 64;
    const int h  = blockIdx.y;
    const int b  = blockIdx.z;
    const int tid = threadIdx.x;
    const float* Qb = Q + (b * NQ) * DMODEL + h * HD;
    const float* Kb = K + (b * SK) * DMODEL + h * HD;
    const float* Vb = V + (b * SK) * DMODEL + h * HD;
    const float* mb = mask + b * SK;

    // Q tile: transposed + swizzled
    #pragma unroll
    for (int it = 0; it < 4; it++) {
        int id = it * 256 + tid;
        int r  = id & 63;
        int c4 = id >> 6;
        float4 v = *(const float4*)(Qb + (n0 + r) * DMODEL + c4 * 4);
        int rb = r >> 2, ro = r & 3;
        #pragma unroll
        for (int j = 0; j < 4; j++) {
            int d  = c4 * 4 + j;
            int ch = (rb + d) & 15;
            Qs[d][ch * 4 + ro] = ((const float*)&v)[j];
        }
    }

    const int tx = tid & 15, ty = tid >> 4;   // score phase: 4x4 micro-tile
    const int rc = tid >> 2, qc = tid & 3;    // softmax/PV: 1 row, 16 cols

    // Per-thread load coordinates for K (transposed store) and V tiles
    int ks_[4], kc4_[4], vs_[4], vc4_[4];
    #pragma unroll
    for (int it = 0; it < 4; it++) {
        int id = it * 256 + tid;
        ks_[it]  = id & 63;  kc4_[it] = id >> 6;   // K: s-major read
        vs_[it]  = id >> 4;  vc4_[it] = id & 15;   // V: row read
    }

    float4 kreg[4], vreg[4];
    float  mreg[4];
    // Prologue: load s0 = 0 tiles
    #pragma unroll
    for (int it = 0; it < 4; it++) {
        kreg[it] = *(const float4*)(Kb + ks_[it] * DMODEL + kc4_[it] * 4);
        vreg[it] = *(const float4*)(Vb + vs_[it] * DMODEL + vc4_[it] * 4);
        mreg[it] = __ldg(mb + vs_[it]);
    }

    float m_i = -1e30f, l_i = 0.f;
    float acc[16];
    #pragma unroll
    for (int j = 0; j < 16; j++) acc[j] = 0.f;

    for (int s0 = 0; s0 < SK; s0 += 64) {
        __syncthreads();  // prev tile's PV reads (and Q stores, iter 0) done
        // Stage K regs -> KP (transposed + swizzled)
        #pragma unroll
        for (int it = 0; it < 4; it++) {
            int s = ks_[it];
            int sb = s >> 2, so = s & 3;
            #pragma unroll
            for (int j = 0; j < 4; j++) {
                int d  = kc4_[it] * 4 + j;
                int ch = (sb + d) & 15;
                KP[d][ch * 4 + so] = ((const float*)&kreg[it])[j];
            }
        }
        // Stage V regs -> Vs (masked, swizzled)
        #pragma unroll
        for (int it = 0; it < 4; it++) {
            int s  = vs_[it];
            int ch = (vc4_[it] + s) & 15;
            float mk = mreg[it];
            float4 v = vreg[it];
            *(float4*)&Vs[s][ch * 4] =
                make_float4(v.x * mk, v.y * mk, v.z * mk, v.w * mk);
        }
        __syncthreads();

        // Prefetch next tile (overlaps with score compute below)
        if (s0 + 64 < SK) {
            #pragma unroll
            for (int it = 0; it < 4; it++) {
                kreg[it] = *(const float4*)(Kb + (s0 + 64 + ks_[it]) * DMODEL + kc4_[it] * 4);
                vreg[it] = *(const float4*)(Vb + (s0 + 64 + vs_[it]) * DMODEL + vc4_[it] * 4);
                mreg[it] = __ldg(mb + s0 + 64 + vs_[it]);
            }
        }

        // Scores: sc[i][j] = sum_d Q[r0+i][d]*K[s0c+j][d]
        float sc[4][4];
        #pragma unroll
        for (int i = 0; i < 4; i++)
            #pragma unroll
            for (int j = 0; j < 4; j++) sc[i][j] = 0.f;
        #pragma unroll 16
        for (int d = 0; d < 64; d++) {
            int cq = (ty + d) & 15;
            float4 qv = *(const float4*)&Qs[d][cq * 4];
            int ck = (tx + d) & 15;
            float4 kv = *(const float4*)&KP[d][ck * 4];
            const float* qa = (const float*)&qv;
            const float* ka = (const float*)&kv;
            #pragma unroll
            for (int i = 0; i < 4; i++)
                #pragma unroll
                for (int j = 0; j < 4; j++)
                    sc[i][j] += qa[i] * ka[j];
        }
        __syncthreads();  // all K reads done; KP becomes P
        #pragma unroll
        for (int j = 0; j < 4; j++) {
            int s = tx * 4 + j;
            float mk = __ldg(mb + s0 + s);
            bool on = (mk != 0.f);
            #pragma unroll
            for (int i = 0; i < 4; i++)
                KP[ty * 4 + i][s] = on ? sc[i][j] * ATTN_SCALE : NEG_BIG;
        }
        __syncthreads();

        // Online softmax on row rc (4 lanes/row, rotated column partition)
        float pvv[16];
        float tmax = -1e30f;
        #pragma unroll
        for (int i = 0; i < 16; i++) {
            int s = (qc * 16 + i + rc) & 63;
            pvv[i] = KP[rc][s];
            tmax = fmaxf(tmax, pvv[i]);
        }
        tmax = fmaxf(tmax, __shfl_xor_sync(0xffffffffu, tmax, 1));
        tmax = fmaxf(tmax, __shfl_xor_sync(0xffffffffu, tmax, 2));
        float m_new = fmaxf(m_i, tmax);
        float corr  = __expf(m_i - m_new);
        float tsum  = 0.f;
        #pragma unroll
        for (int i = 0; i < 16; i++) {
            int s = (qc * 16 + i + rc) & 63;
            float e = __expf(pvv[i] - m_new);
            KP[rc][s] = e;
            tsum += e;
        }
        tsum += __shfl_xor_sync(0xffffffffu, tsum, 1);
        tsum += __shfl_xor_sync(0xffffffffu, tsum, 2);
        m_i = m_new;
        l_i = l_i * corr + tsum;
        #pragma unroll
        for (int j = 0; j < 16; j++) acc[j] *= corr;
        __syncwarp();

        // PV: acc[c] += sum_s P[rc][s] * V[s][c], rotated s for bank spread
        #pragma unroll 8
        for (int i = 0; i < 64; i++) {
            int s = (i + rc) & 63;
            float p = KP[rc][s];
            #pragma unroll
            for (int j = 0; j < 4; j++) {
                int ch = (qc * 4 + j + s) & 15;
                float4 v = *(const float4*)&Vs[s][ch * 4];
                acc[j*4+0] += p * v.x;
                acc[j*4+1] += p * v.y;
                acc[j*4+2] += p * v.z;
                acc[j*4+3] += p * v.w;
            }
        }
    }

    float inv = 1.f / l_i;
    float* Ob = O + (b * NQ + n0 + rc) * DMODEL + h * HD + qc * 16;
    #pragma unroll
    for (int j = 0; j < 4; j++) {
        float4 v = make_float4(acc[j*4+0]*inv, acc[j*4+1]*inv,
                               acc[j*4+2]*inv, acc[j*4+3]*inv);
        *(float4*)(Ob + j * 4) = v;
    }
}

// ---------------------------------------------------------------------------
extern "C" void kernel_launch(void* const* d_in, const int* in_sizes, int n_in,
                              void* d_out, int out_size)
{
    const float* query = (const float*)d_in[0];
    const float* key   = (const float*)d_in[1];
    const float* value = (const float*)d_in[2];
    const float* maskp = (const float*)d_in[3];
    const float* Wq    = (const float*)d_in[4];
    const float* Wk    = (const float*)d_in[5];
    const float* Wv    = (const float*)d_in[6];
    const float* Wo    = (const float*)d_in[7];
    const float* bo    = (const float*)d_in[8];

    float *Qp, *Kp, *Vp, *AO;
    cudaGetSymbolAddress((void**)&Qp, g_Qp);
    cudaGetSymbolAddress((void**)&Kp, g_Kp);
    cudaGetSymbolAddress((void**)&Vp, g_Vp);
    cudaGetSymbolAddress((void**)&AO, g_AO);

    dim3 blk(256);
    gemm_xwt<false><<<dim3(DMODEL/128, (BATCH*NQ)/128), blk>>>(
        query, Wq, nullptr, Qp, BATCH*NQ, DMODEL, DMODEL);
    gemm_xwt<false><<<dim3(DMODEL/128, (BATCH*SK)/128), blk>>>(
        key,   Wk, nullptr, Kp, BATCH*SK, DMODEL, DMODEL);
    gemm_xwt<false><<<dim3(DMODEL/128, (BATCH*SK)/128), blk>>>(
        value, Wv, nullptr, Vp, BATCH*SK, DMODEL, DMODEL);
    attn_fwd<<<dim3(NQ/64, NH, BATCH), blk>>>(Qp, Kp, Vp, maskp, AO);
    gemm_xwt<true><<<dim3(DMODEL/128, (BATCH*NQ)/128), blk>>>(
        AO, Wo, bo, (float*)d_out, BATCH*NQ, DMODEL, DMODEL);
}

// round 6
// speedup vs baseline: 1.6251x; 1.6251x over previous
#include <cuda_runtime.h>

#define NH      12
#define DMODEL  768
#define HD      64
#define BATCH   2
#define NQ      1024
#define SK      4096
#define ATTN_SCALE 0.125f

// Scratch (allocation-free rule: __device__ globals)
__device__ float g_Qp[BATCH * NQ * DMODEL];
__device__ float g_Kp[BATCH * SK * DMODEL];
__device__ float g_Vp[BATCH * SK * DMODEL];
__device__ float g_AO[BATCH * NQ * DMODEL];

// ---------------------------------------------------------------------------
// C[M][N] = A[M][K] @ W[N][K]^T (+ bias). 128x128x16 tile, 256 thr, 8x8/thread.
// k-major smem with chunk-XOR swizzle; register-staged double buffering.
// ---------------------------------------------------------------------------
template<bool BIAS>
__global__ __launch_bounds__(256) void gemm_xwt(
    const float* __restrict__ A, const float* __restrict__ W,
    const float* __restrict__ bias, float* __restrict__ C,
    int M, int N, int K)
{
    __shared__ float As[16][128];
    __shared__ float Bs[16][128];
    const int m0 = blockIdx.y * 128;
    const int n0 = blockIdx.x * 128;
    const int tid = threadIdx.x;
    const int tx = tid & 15;
    const int ty = tid >> 4;

    float acc[8][8];
    #pragma unroll
    for (int i = 0; i < 8; i++)
        #pragma unroll
        for (int j = 0; j < 8; j++) acc[i][j] = 0.f;

    int lm[2], lc4[2];
    #pragma unroll
    for (int it = 0; it < 2; it++) {
        int id = it * 256 + tid;
        lm[it]  = id >> 2;
        lc4[it] = id & 3;
    }

    float4 av[2], wv[2];
    #pragma unroll
    for (int it = 0; it < 2; it++) {
        av[it] = *(const float4*)(A + (m0 + lm[it]) * K + lc4[it] * 4);
        wv[it] = *(const float4*)(W + (n0 + lm[it]) * K + lc4[it] * 4);
    }

    for (int kt = 0; kt < K; kt += 16) {
        #pragma unroll
        for (int it = 0; it < 2; it++) {
            int m = lm[it];
            int mb = m >> 2, mo = m & 3;
            #pragma unroll
            for (int j = 0; j < 4; j++) {
                int k  = lc4[it] * 4 + j;
                int ch = (mb + k) & 31;
                As[k][ch * 4 + mo] = ((const float*)&av[it])[j];
                Bs[k][ch * 4 + mo] = ((const float*)&wv[it])[j];
            }
        }
        __syncthreads();

        if (kt + 16 < K) {
            #pragma unroll
            for (int it = 0; it < 2; it++) {
                av[it] = *(const float4*)(A + (m0 + lm[it]) * K + kt + 16 + lc4[it] * 4);
                wv[it] = *(const float4*)(W + (n0 + lm[it]) * K + kt + 16 + lc4[it] * 4);
            }
        }

        #pragma unroll
        for (int k = 0; k < 16; k++) {
            float a[8], b[8];
            #pragma unroll
            for (int hh = 0; hh < 2; hh++) {
                int cha = (hh * 16 + ty + k) & 31;
                float4 a4 = *(const float4*)&As[k][cha * 4];
                a[hh*4+0] = a4.x; a[hh*4+1] = a4.y; a[hh*4+2] = a4.z; a[hh*4+3] = a4.w;
                int chb = (hh * 16 + tx + k) & 31;
                float4 b4 = *(const float4*)&Bs[k][chb * 4];
                b[hh*4+0] = b4.x; b[hh*4+1] = b4.y; b[hh*4+2] = b4.z; b[hh*4+3] = b4.w;
            }
            #pragma unroll
            for (int i = 0; i < 8; i++)
                #pragma unroll
                for (int j = 0; j < 8; j++)
                    acc[i][j] += a[i] * b[j];
        }
        __syncthreads();
    }

    #pragma unroll
    for (int hi = 0; hi < 2; hi++)
        #pragma unroll
        for (int i = 0; i < 4; i++) {
            int row = m0 + hi * 64 + ty * 4 + i;
            #pragma unroll
            for (int hj = 0; hj < 2; hj++) {
                int col = n0 + hj * 64 + tx * 4;
                float4 v;
                v.x = acc[hi*4+i][hj*4+0];
                v.y = acc[hi*4+i][hj*4+1];
                v.z = acc[hi*4+i][hj*4+2];
                v.w = acc[hi*4+i][hj*4+3];
                if (BIAS) {
                    v.x += bias[col+0]; v.y += bias[col+1];
                    v.z += bias[col+2]; v.w += bias[col+3];
                }
                *(float4*)(C + row * N + col) = v;
            }
        }
}

// ---------------------------------------------------------------------------
// attn_fwd v2: 128 threads, Q-tile 64, S-tile 128.
//  - Scores: 8x8 per-thread micro-tile; Qs/KP d-major chunk-XOR swizzle.
//  - KP reused as P[64][128], rotated phys = (c + 4r) & 127.
//  - Softmax: 2 thr/row; masked scores -> -1e30 pre-max, m_new clamped
//    >= -1e29 so masked exp underflows to exactly 0; l==0 -> inv=0.
//  - PV: 8 rows x 4 cols per thread, P loaded as float4 per 4 s-steps.
// Dynamic smem ~81KB, 2 CTA/SM.
// ---------------------------------------------------------------------------
__global__ __launch_bounds__(128, 2) void attn_fwd(
    const float* __restrict__ Q, const float* __restrict__ K,
    const float* __restrict__ V, const float* __restrict__ mask,
    float* __restrict__ O)
{
    extern __shared__ float sm[];
    float* const Qs = sm;           // [64][64]   d-major, swz mod 16
    float* const KP = sm + 4096;    // [64][128]  K d-major swz mod 32 / P rotated
    float* const Vs = sm + 12288;   // [128][64]  row-major, chunk swz (c+s)&15
    float* const Ms = sm + 20480;   // [128]
    float* const Cs = sm + 20608;   // [64] per-row rescale
    float* const Ls = sm + 20672;   // [64] per-row 1/l

    const int n0 = blockIdx.x * 64;
    const int h  = blockIdx.y;
    const int b  = blockIdx.z;
    const int tid = threadIdx.x;
    const int ty = tid >> 4, tx = tid & 15;   // score/PV grid 8x16
    const int rc = tid >> 1, qc = tid & 1;    // softmax: 2 thr/row

    const float* Qb = Q + (size_t)b * NQ * DMODEL + h * HD;
    const float* Kb = K + (size_t)b * SK * DMODEL + h * HD;
    const float* Vb = V + (size_t)b * SK * DMODEL + h * HD;
    const float* mb = mask + (size_t)b * SK;

    // ---- Q tile load: transposed to d-major, chunk swizzle mod 16
    {
        int r = tid & 63;
        int ch = tid >> 6;               // 0/1
        int rb = r >> 2, o = r & 3;
        const float* qr = Qb + (size_t)(n0 + r) * DMODEL;
        #pragma unroll
        for (int it = 0; it < 8; it++) {
            int c4 = it * 2 + ch;        // 0..15
            float4 v = *(const float4*)(qr + c4 * 4);
            #pragma unroll
            for (int j = 0; j < 4; j++) {
                int d = c4 * 4 + j;
                Qs[d * 64 + ((rb + d) & 15) * 4 + o] = ((const float*)&v)[j];
            }
        }
    }

    float m_i = -1e30f, l_i = 0.f;
    float acc[8][4];
    #pragma unroll
    for (int i = 0; i < 8; i++)
        #pragma unroll
        for (int j = 0; j < 4; j++) acc[i][j] = 0.f;

    for (int s0 = 0; s0 < SK; s0 += 128) {
        __syncthreads();   // prev PV done with KP/Vs (covers Q stores on iter 0)

        // K tile -> KP d-major [64][128], chunk swizzle mod 32
        {
            int s = tid;                  // 0..127
            int sb = s >> 2, o = s & 3;
            const float* kr = Kb + (size_t)(s0 + s) * DMODEL;
            #pragma unroll
            for (int c4 = 0; c4 < 16; c4++) {
                float4 v = *(const float4*)(kr + c4 * 4);
                #pragma unroll
                for (int j = 0; j < 4; j++) {
                    int d = c4 * 4 + j;
                    KP[d * 128 + ((sb + d) & 31) * 4 + o] = ((const float*)&v)[j];
                }
            }
        }
        // V tile -> Vs [128][64], chunk swizzled by +s (coalesced gmem reads)
        {
            int c4 = tid & 15;
            int sh = tid >> 4;            // 0..7
            #pragma unroll
            for (int it = 0; it < 16; it++) {
                int s = it * 8 + sh;
                float4 v = *(const float4*)(Vb + (size_t)(s0 + s) * DMODEL + c4 * 4);
                *(float4*)&Vs[s * 64 + ((c4 + s) & 15) * 4] = v;
            }
        }
        Ms[tid] = __ldg(mb + s0 + tid);
        __syncthreads();

        // ---- scores: sc[8][8]
        float sc[8][8];
        #pragma unroll
        for (int i = 0; i < 8; i++)
            #pragma unroll
            for (int j = 0; j < 8; j++) sc[i][j] = 0.f;

        #pragma unroll 4
        for (int d = 0; d < 64; d++) {
            const float* qrow = Qs + d * 64;
            const float* krow = KP + d * 128;
            float4 q0 = *(const float4*)(qrow + ((ty + d) & 15) * 4);
            float4 q1 = *(const float4*)(qrow + ((ty + 8 + d) & 15) * 4);
            float4 k0 = *(const float4*)(krow + ((tx + d) & 31) * 4);
            float4 k1 = *(const float4*)(krow + ((tx + 16 + d) & 31) * 4);
            float a[8] = {q0.x,q0.y,q0.z,q0.w, q1.x,q1.y,q1.z,q1.w};
            float bb[8] = {k0.x,k0.y,k0.z,k0.w, k1.x,k1.y,k1.z,k1.w};
            #pragma unroll
            for (int i = 0; i < 8; i++)
                #pragma unroll
                for (int j = 0; j < 8; j++)
                    sc[i][j] += a[i] * bb[j];
        }
        __syncthreads();   // K reads done; KP becomes P

        // ---- P store: scaled, rotated phys = (c + 4r) & 127
        #pragma unroll
        for (int i = 0; i < 8; i++) {
            int r = ty * 4 + (i & 3) + (i >> 2) * 32;
            float* pr = KP + r * 128;
            #pragma unroll
            for (int hh = 0; hh < 2; hh++) {
                int c = tx * 4 + hh * 64;
                int phys = (c + 4 * r) & 127;
                float4 v = make_float4(sc[i][hh*4+0] * ATTN_SCALE,
                                       sc[i][hh*4+1] * ATTN_SCALE,
                                       sc[i][hh*4+2] * ATTN_SCALE,
                                       sc[i][hh*4+3] * ATTN_SCALE);
                *(float4*)(pr + phys) = v;
            }
        }
        __syncthreads();

        // ---- online softmax: row rc, half qc (64 values each)
        float4 pv4[16];
        float tmax = -1e30f;
        #pragma unroll
        for (int i = 0; i < 16; i++) {
            int slog = qc * 64 + i * 4;
            int phys = (slog + 4 * rc) & 127;
            float4 p = *(const float4*)(KP + rc * 128 + phys);
            float4 mk = *(const float4*)(Ms + slog);
            p.x = (mk.x != 0.f) ? p.x : -1e30f;
            p.y = (mk.y != 0.f) ? p.y : -1e30f;
            p.z = (mk.z != 0.f) ? p.z : -1e30f;
            p.w = (mk.w != 0.f) ? p.w : -1e30f;
            pv4[i] = p;
            tmax = fmaxf(tmax, fmaxf(fmaxf(p.x, p.y), fmaxf(p.z, p.w)));
        }
        tmax = fmaxf(tmax, __shfl_xor_sync(0xffffffffu, tmax, 1));
        // clamp keeps masked exp underflowing to exactly 0 even if the whole
        // running row is masked (then l stays 0 -> inv 0 -> output 0)
        float m_new = fmaxf(fmaxf(m_i, tmax), -1e29f);
        float corr  = __expf(m_i - m_new);
        float tsum  = 0.f;
        #pragma unroll
        for (int i = 0; i < 16; i++) {
            int slog = qc * 64 + i * 4;
            int phys = (slog + 4 * rc) & 127;
            float4 p = pv4[i];
            float4 e;
            e.x = __expf(p.x - m_new);
            e.y = __expf(p.y - m_new);
            e.z = __expf(p.z - m_new);
            e.w = __expf(p.w - m_new);
            tsum += (e.x + e.y) + (e.z + e.w);
            *(float4*)(KP + rc * 128 + phys) = e;
        }
        tsum += __shfl_xor_sync(0xffffffffu, tsum, 1);
        l_i = l_i * corr + tsum;
        m_i = m_new;
        if (qc == 0) Cs[rc] = corr;
        __syncthreads();

        // ---- PV: acc[8 rows][4 cols], P as float4 per 4 s-steps
        #pragma unroll
        for (int i = 0; i < 8; i++) {
            int r = ty * 4 + (i & 3) + (i >> 2) * 32;
            float cr = Cs[r];
            #pragma unroll
            for (int j = 0; j < 4; j++) acc[i][j] *= cr;
        }
        #pragma unroll 2
        for (int sc4 = 0; sc4 < 32; sc4++) {
            int s = sc4 * 4;
            float4 p[8];
            #pragma unroll
            for (int i = 0; i < 8; i++) {
                int r = ty * 4 + (i & 3) + (i >> 2) * 32;
                p[i] = *(const float4*)(KP + r * 128 + ((s + 4 * r) & 127));
            }
            #pragma unroll
            for (int k = 0; k < 4; k++) {
                int ss = s + k;
                float4 v = *(const float4*)(Vs + ss * 64 + ((tx + ss) & 15) * 4);
                #pragma unroll
                for (int i = 0; i < 8; i++) {
                    float pw = ((const float*)&p[i])[k];
                    acc[i][0] += pw * v.x;
                    acc[i][1] += pw * v.y;
                    acc[i][2] += pw * v.z;
                    acc[i][3] += pw * v.w;
                }
            }
        }
    }

    if (qc == 0) Ls[rc] = (l_i > 0.f) ? (1.f / l_i) : 0.f;
    __syncthreads();

    #pragma unroll
    for (int i = 0; i < 8; i++) {
        int r = ty * 4 + (i & 3) + (i >> 2) * 32;
        float inv = Ls[r];
        float4 v = make_float4(acc[i][0] * inv, acc[i][1] * inv,
                               acc[i][2] * inv, acc[i][3] * inv);
        *(float4*)(O + (size_t)(b * NQ + n0 + r) * DMODEL + h * HD + tx * 4) = v;
    }
}

// ---------------------------------------------------------------------------
extern "C" void kernel_launch(void* const* d_in, const int* in_sizes, int n_in,
                              void* d_out, int out_size)
{
    const float* query = (const float*)d_in[0];
    const float* key   = (const float*)d_in[1];
    const float* value = (const float*)d_in[2];
    const float* maskp = (const float*)d_in[3];
    const float* Wq    = (const float*)d_in[4];
    const float* Wk    = (const float*)d_in[5];
    const float* Wv    = (const float*)d_in[6];
    const float* Wo    = (const float*)d_in[7];
    const float* bo    = (const float*)d_in[8];

    float *Qp, *Kp, *Vp, *AO;
    cudaGetSymbolAddress((void**)&Qp, g_Qp);
    cudaGetSymbolAddress((void**)&Kp, g_Kp);
    cudaGetSymbolAddress((void**)&Vp, g_Vp);
    cudaGetSymbolAddress((void**)&AO, g_AO);

    const int attn_smem = 20736 * 4;   // 82944 B dynamic
    cudaFuncSetAttribute(attn_fwd,
                         cudaFuncAttributeMaxDynamicSharedMemorySize, attn_smem);

    dim3 blk(256);
    gemm_xwt<false><<<dim3(DMODEL/128, (BATCH*NQ)/128), blk>>>(
        query, Wq, nullptr, Qp, BATCH*NQ, DMODEL, DMODEL);
    gemm_xwt<false><<<dim3(DMODEL/128, (BATCH*SK)/128), blk>>>(
        key,   Wk, nullptr, Kp, BATCH*SK, DMODEL, DMODEL);
    gemm_xwt<false><<<dim3(DMODEL/128, (BATCH*SK)/128), blk>>>(
        value, Wv, nullptr, Vp, BATCH*SK, DMODEL, DMODEL);
    attn_fwd<<<dim3(NQ/64, NH, BATCH), 128, attn_smem>>>(Qp, Kp, Vp, maskp, AO);
    gemm_xwt<true><<<dim3(DMODEL/128, (BATCH*NQ)/128), blk>>>(
        AO, Wo, bo, (float*)d_out, BATCH*NQ, DMODEL, DMODEL);
}

// round 10
// speedup vs baseline: 2.3526x; 1.4476x over previous
#include <cuda_runtime.h>
#include <cstdint>

#define NH      12
#define DMODEL  768
#define HD      64
#define BATCH   2
#define NQ      1024
#define SK      4096
#define ATTN_SCALE 0.125f

// Scratch (allocation-free rule: __device__ globals)
__device__ float g_Qp[BATCH * NQ * DMODEL];
__device__ float g_Kp[BATCH * SK * DMODEL];
__device__ float g_Vp[BATCH * SK * DMODEL];
__device__ float g_AO[BATCH * NQ * DMODEL];

// ---------------------------------------------------------------------------
// TF32 helpers
// ---------------------------------------------------------------------------
__device__ __forceinline__ uint32_t f2tf32(float x) {
    uint32_t r;
    asm("cvt.rna.tf32.f32 %0, %1;" : "=r"(r) : "f"(x));
    return r;
}

__device__ __forceinline__ void mma_tf32(float* c, const uint32_t* a, const uint32_t* b) {
    asm volatile(
        "mma.sync.aligned.m16n8k8.row.col.f32.tf32.tf32.f32 "
        "{%0,%1,%2,%3}, {%4,%5,%6,%7}, {%8,%9}, {%0,%1,%2,%3};"
        : "+f"(c[0]), "+f"(c[1]), "+f"(c[2]), "+f"(c[3])
        : "r"(a[0]), "r"(a[1]), "r"(a[2]), "r"(a[3]),
          "r"(b[0]), "r"(b[1]));
}

// ---------------------------------------------------------------------------
// C[M][N] = A[M][K] @ W[N][K]^T (+ bias), TF32 tensor cores.
// CTA 128x128, 256 thr = 8 warps (2m x 4n), warp tile 64x32,
// 16 x m16n8k8 mma per k8-step. Smem m-major with pad 20: frag-read bank =
// (20*(lane>>2) + (lane&3)) mod 32 -> all 32 lanes distinct, conflict-free.
// Register-staged double buffering of gmem loads.
// ---------------------------------------------------------------------------
template<bool BIAS>
__global__ __launch_bounds__(256, 2) void gemm_tf32(
    const float* __restrict__ A, const float* __restrict__ W,
    const float* __restrict__ bias, float* __restrict__ C,
    int M, int N, int K)
{
    __shared__ float As[128 * 20];
    __shared__ float Bs[128 * 20];
    const int m0 = blockIdx.y * 128;
    const int n0 = blockIdx.x * 128;
    const int tid  = threadIdx.x;
    const int wid  = tid >> 5;
    const int lane = tid & 31;
    const int warp_m = wid >> 2;      // 0..1
    const int warp_n = wid & 3;       // 0..3
    const int gid = lane >> 2;        // 0..7
    const int tig = lane & 3;         // 0..3

    float acc[4][4][4];
    #pragma unroll
    for (int mt = 0; mt < 4; mt++)
        #pragma unroll
        for (int nt = 0; nt < 4; nt++)
            #pragma unroll
            for (int c = 0; c < 4; c++) acc[mt][nt][c] = 0.f;

    int lm[2], lc4[2];
    #pragma unroll
    for (int it = 0; it < 2; it++) {
        int id = it * 256 + tid;
        lm[it]  = id >> 2;
        lc4[it] = id & 3;
    }

    float4 av[2], wv[2];
    #pragma unroll
    for (int it = 0; it < 2; it++) {
        av[it] = *(const float4*)(A + (m0 + lm[it]) * K + lc4[it] * 4);
        wv[it] = *(const float4*)(W + (n0 + lm[it]) * K + lc4[it] * 4);
    }

    for (int kt = 0; kt < K; kt += 16) {
        #pragma unroll
        for (int it = 0; it < 2; it++) {
            *(float4*)&As[lm[it] * 20 + lc4[it] * 4] = av[it];
            *(float4*)&Bs[lm[it] * 20 + lc4[it] * 4] = wv[it];
        }
        __syncthreads();

        if (kt + 16 < K) {
            #pragma unroll
            for (int it = 0; it < 2; it++) {
                av[it] = *(const float4*)(A + (m0 + lm[it]) * K + kt + 16 + lc4[it] * 4);
                wv[it] = *(const float4*)(W + (n0 + lm[it]) * K + kt + 16 + lc4[it] * 4);
            }
        }

        #pragma unroll
        for (int ks = 0; ks < 16; ks += 8) {
            uint32_t afr[4][4];
            #pragma unroll
            for (int mt = 0; mt < 4; mt++) {
                int row = warp_m * 64 + mt * 16 + gid;
                afr[mt][0] = f2tf32(As[row       * 20 + ks + tig]);
                afr[mt][1] = f2tf32(As[(row + 8) * 20 + ks + tig]);
                afr[mt][2] = f2tf32(As[row       * 20 + ks + 4 + tig]);
                afr[mt][3] = f2tf32(As[(row + 8) * 20 + ks + 4 + tig]);
            }
            uint32_t bfr[4][2];
            #pragma unroll
            for (int nt = 0; nt < 4; nt++) {
                int col = warp_n * 32 + nt * 8 + gid;
                bfr[nt][0] = f2tf32(Bs[col * 20 + ks + tig]);
                bfr[nt][1] = f2tf32(Bs[col * 20 + ks + 4 + tig]);
            }
            #pragma unroll
            for (int mt = 0; mt < 4; mt++)
                #pragma unroll
                for (int nt = 0; nt < 4; nt++)
                    mma_tf32(acc[mt][nt], afr[mt], bfr[nt]);
        }
        __syncthreads();
    }

    #pragma unroll
    for (int mt = 0; mt < 4; mt++) {
        int row = m0 + warp_m * 64 + mt * 16 + gid;
        #pragma unroll
        for (int nt = 0; nt < 4; nt++) {
            int col = n0 + warp_n * 32 + nt * 8 + 2 * tig;
            float b0 = 0.f, b1 = 0.f;
            if (BIAS) { b0 = bias[col]; b1 = bias[col + 1]; }
            float2 v0 = make_float2(acc[mt][nt][0] + b0, acc[mt][nt][1] + b1);
            float2 v1 = make_float2(acc[mt][nt][2] + b0, acc[mt][nt][3] + b1);
            *(float2*)(C + (size_t)row * N + col)       = v0;
            *(float2*)(C + (size_t)(row + 8) * N + col) = v1;
        }
    }
}

// ---------------------------------------------------------------------------
// attn_fwd v3: 256 threads, Q-tile 64, S-tile 128 (same smem plan as v2,
// double the warps to fix the measured latency limit: occ 11.5% / issue 63.5%).
//  - Scores: 4x8 per-thread micro-tile (rows ty*4+i, cols tx*4+{0,64}).
//  - KP reused as P[64][128], rotated phys = (c + 4r) & 127.
//  - Softmax: 4 thr/row (qc = tid&3, 32 values each).
//  - PV: 4 rows x 4 cols per thread, P as float4 per 4 s-steps.
// Masked handling: masked scores -> -1e30 pre-max, m_new clamped >= -1e29 so
// masked exp underflows to exactly 0; l==0 -> inv=0 (fully-masked rows).
// ---------------------------------------------------------------------------
__global__ __launch_bounds__(256, 2) void attn_fwd(
    const float* __restrict__ Q, const float* __restrict__ K,
    const float* __restrict__ V, const float* __restrict__ mask,
    float* __restrict__ O)
{
    extern __shared__ float sm[];
    float* const Qs = sm;           // [64][64]   d-major, swz mod 16
    float* const KP = sm + 4096;    // [64][128]  K d-major swz mod 32 / P rotated
    float* const Vs = sm + 12288;   // [128][64]  row-major, chunk swz (c+s)&15
    float* const Ms = sm + 20480;   // [128]
    float* const Cs = sm + 20608;   // [64] per-row rescale
    float* const Ls = sm + 20672;   // [64] per-row 1/l

    const int n0 = blockIdx.x * 64;
    const int h  = blockIdx.y;
    const int b  = blockIdx.z;
    const int tid = threadIdx.x;
    const int ty = tid >> 4, tx = tid & 15;   // 16x16 grid
    const int rc = tid >> 2, qc = tid & 3;    // softmax: 4 thr/row

    const float* Qb = Q + (size_t)b * NQ * DMODEL + h * HD;
    const float* Kb = K + (size_t)b * SK * DMODEL + h * HD;
    const float* Vb = V + (size_t)b * SK * DMODEL + h * HD;
    const float* mb = mask + (size_t)b * SK;

    // ---- Q tile load: transposed to d-major, chunk swizzle mod 16
    {
        int r = tid & 63;
        int ch = tid >> 6;               // 0..3
        int rb = r >> 2, o = r & 3;
        const float* qr = Qb + (size_t)(n0 + r) * DMODEL;
        #pragma unroll
        for (int it = 0; it < 4; it++) {
            int c4 = it * 4 + ch;        // 0..15
            float4 v = *(const float4*)(qr + c4 * 4);
            #pragma unroll
            for (int j = 0; j < 4; j++) {
                int d = c4 * 4 + j;
                Qs[d * 64 + ((rb + d) & 15) * 4 + o] = ((const float*)&v)[j];
            }
        }
    }

    float m_i = -1e30f, l_i = 0.f;
    float acc[4][4];
    #pragma unroll
    for (int i = 0; i < 4; i++)
        #pragma unroll
        for (int j = 0; j < 4; j++) acc[i][j] = 0.f;

    for (int s0 = 0; s0 < SK; s0 += 128) {
        __syncthreads();   // prev PV done with KP/Vs (covers Q stores on iter 0)

        // K tile -> KP d-major [64][128], chunk swizzle mod 32
        {
            int s = tid & 127;
            int ch = tid >> 7;            // 0/1
            int sb = s >> 2, o = s & 3;
            const float* kr = Kb + (size_t)(s0 + s) * DMODEL;
            #pragma unroll
            for (int it = 0; it < 8; it++) {
                int c4 = it * 2 + ch;     // 0..15
                float4 v = *(const float4*)(kr + c4 * 4);
                #pragma unroll
                for (int j = 0; j < 4; j++) {
                    int d = c4 * 4 + j;
                    KP[d * 128 + ((sb + d) & 31) * 4 + o] = ((const float*)&v)[j];
                }
            }
        }
        // V tile -> Vs [128][64], chunk swizzled by +s
        {
            int c4 = tid & 15;
            int sh = tid >> 4;            // 0..15
            #pragma unroll
            for (int it = 0; it < 8; it++) {
                int s = it * 16 + sh;
                float4 v = *(const float4*)(Vb + (size_t)(s0 + s) * DMODEL + c4 * 4);
                *(float4*)&Vs[s * 64 + ((c4 + s) & 15) * 4] = v;
            }
        }
        if (tid < 128) Ms[tid] = __ldg(mb + s0 + tid);
        __syncthreads();

        // ---- scores: sc[4][8]  (rows ty*4+i, cols tx*4+{0,64})
        float sc[4][8];
        #pragma unroll
        for (int i = 0; i < 4; i++)
            #pragma unroll
            for (int j = 0; j < 8; j++) sc[i][j] = 0.f;

        #pragma unroll 4
        for (int d = 0; d < 64; d++) {
            const float* qrow = Qs + d * 64;
            const float* krow = KP + d * 128;
            float4 q0 = *(const float4*)(qrow + ((ty + d) & 15) * 4);
            float4 k0 = *(const float4*)(krow + ((tx + d) & 31) * 4);
            float4 k1 = *(const float4*)(krow + ((tx + 16 + d) & 31) * 4);
            float a[4] = {q0.x, q0.y, q0.z, q0.w};
            float bb[8] = {k0.x,k0.y,k0.z,k0.w, k1.x,k1.y,k1.z,k1.w};
            #pragma unroll
            for (int i = 0; i < 4; i++)
                #pragma unroll
                for (int j = 0; j < 8; j++)
                    sc[i][j] += a[i] * bb[j];
        }
        __syncthreads();   // K reads done; KP becomes P

        // ---- P store: scaled, rotated phys = (c + 4r) & 127
        #pragma unroll
        for (int i = 0; i < 4; i++) {
            int r = ty * 4 + i;
            float* pr = KP + r * 128;
            #pragma unroll
            for (int hh = 0; hh < 2; hh++) {
                int c = tx * 4 + hh * 64;
                int phys = (c + 4 * r) & 127;
                float4 v = make_float4(sc[i][hh*4+0] * ATTN_SCALE,
                                       sc[i][hh*4+1] * ATTN_SCALE,
                                       sc[i][hh*4+2] * ATTN_SCALE,
                                       sc[i][hh*4+3] * ATTN_SCALE);
                *(float4*)(pr + phys) = v;
            }
        }
        __syncthreads();

        // ---- online softmax: row rc, quarter qc (32 values each)
        float4 pv4[8];
        float tmax = -1e30f;
        #pragma unroll
        for (int i = 0; i < 8; i++) {
            int slog = qc * 32 + i * 4;
            int phys = (slog + 4 * rc) & 127;
            float4 p = *(const float4*)(KP + rc * 128 + phys);
            float4 mk = *(const float4*)(Ms + slog);
            p.x = (mk.x != 0.f) ? p.x : -1e30f;
            p.y = (mk.y != 0.f) ? p.y : -1e30f;
            p.z = (mk.z != 0.f) ? p.z : -1e30f;
            p.w = (mk.w != 0.f) ? p.w : -1e30f;
            pv4[i] = p;
            tmax = fmaxf(tmax, fmaxf(fmaxf(p.x, p.y), fmaxf(p.z, p.w)));
        }
        tmax = fmaxf(tmax, __shfl_xor_sync(0xffffffffu, tmax, 1));
        tmax = fmaxf(tmax, __shfl_xor_sync(0xffffffffu, tmax, 2));
        float m_new = fmaxf(fmaxf(m_i, tmax), -1e29f);
        float corr  = __expf(m_i - m_new);
        float tsum  = 0.f;
        #pragma unroll
        for (int i = 0; i < 8; i++) {
            int slog = qc * 32 + i * 4;
            int phys = (slog + 4 * rc) & 127;
            float4 p = pv4[i];
            float4 e;
            e.x = __expf(p.x - m_new);
            e.y = __expf(p.y - m_new);
            e.z = __expf(p.z - m_new);
            e.w = __expf(p.w - m_new);
            tsum += (e.x + e.y) + (e.z + e.w);
            *(float4*)(KP + rc * 128 + phys) = e;
        }
        tsum += __shfl_xor_sync(0xffffffffu, tsum, 1);
        tsum += __shfl_xor_sync(0xffffffffu, tsum, 2);
        l_i = l_i * corr + tsum;
        m_i = m_new;
        if (qc == 0) Cs[rc] = corr;
        __syncthreads();

        // ---- PV: acc[4 rows][4 cols], P as float4 per 4 s-steps
        #pragma unroll
        for (int i = 0; i < 4; i++) {
            float cr = Cs[ty * 4 + i];
            #pragma unroll
            for (int j = 0; j < 4; j++) acc[i][j] *= cr;
        }
        #pragma unroll 4
        for (int sc4 = 0; sc4 < 32; sc4++) {
            int s = sc4 * 4;
            float4 p[4];
            #pragma unroll
            for (int i = 0; i < 4; i++) {
                int r = ty * 4 + i;
                p[i] = *(const float4*)(KP + r * 128 + ((s + 4 * r) & 127));
            }
            #pragma unroll
            for (int k = 0; k < 4; k++) {
                int ss = s + k;
                float4 v = *(const float4*)(Vs + ss * 64 + ((tx + ss) & 15) * 4);
                #pragma unroll
                for (int i = 0; i < 4; i++) {
                    float pw = ((const float*)&p[i])[k];
                    acc[i][0] += pw * v.x;
                    acc[i][1] += pw * v.y;
                    acc[i][2] += pw * v.z;
                    acc[i][3] += pw * v.w;
                }
            }
        }
    }

    if (qc == 0) Ls[rc] = (l_i > 0.f) ? (1.f / l_i) : 0.f;
    __syncthreads();

    #pragma unroll
    for (int i = 0; i < 4; i++) {
        int r = ty * 4 + i;
        float inv = Ls[r];
        float4 v = make_float4(acc[i][0] * inv, acc[i][1] * inv,
                               acc[i][2] * inv, acc[i][3] * inv);
        *(float4*)(O + (size_t)(b * NQ + n0 + r) * DMODEL + h * HD + tx * 4) = v;
    }
}

// ---------------------------------------------------------------------------
extern "C" void kernel_launch(void* const* d_in, const int* in_sizes, int n_in,
                              void* d_out, int out_size)
{
    const float* query = (const float*)d_in[0];
    const float* key   = (const float*)d_in[1];
    const float* value = (const float*)d_in[2];
    const float* maskp = (const float*)d_in[3];
    const float* Wq    = (const float*)d_in[4];
    const float* Wk    = (const float*)d_in[5];
    const float* Wv    = (const float*)d_in[6];
    const float* Wo    = (const float*)d_in[7];
    const float* bo    = (const float*)d_in[8];

    float *Qp, *Kp, *Vp, *AO;
    cudaGetSymbolAddress((void**)&Qp, g_Qp);
    cudaGetSymbolAddress((void**)&Kp, g_Kp);
    cudaGetSymbolAddress((void**)&Vp, g_Vp);
    cudaGetSymbolAddress((void**)&AO, g_AO);

    const int attn_smem = 20736 * 4;   // 82944 B dynamic
    cudaFuncSetAttribute(attn_fwd,
                         cudaFuncAttributeMaxDynamicSharedMemorySize, attn_smem);

    dim3 blk(256);
    gemm_tf32<false><<<dim3(DMODEL/128, (BATCH*NQ)/128), blk>>>(
        query, Wq, nullptr, Qp, BATCH*NQ, DMODEL, DMODEL);
    gemm_tf32<false><<<dim3(DMODEL/128, (BATCH*SK)/128), blk>>>(
        key,   Wk, nullptr, Kp, BATCH*SK, DMODEL, DMODEL);
    gemm_tf32<false><<<dim3(DMODEL/128, (BATCH*SK)/128), blk>>>(
        value, Wv, nullptr, Vp, BATCH*SK, DMODEL, DMODEL);
    attn_fwd<<<dim3(NQ/64, NH, BATCH), 256, attn_smem>>>(Qp, Kp, Vp, maskp, AO);
    gemm_tf32<true><<<dim3(DMODEL/128, (BATCH*NQ)/128), blk>>>(
        AO, Wo, bo, (float*)d_out, BATCH*NQ, DMODEL, DMODEL);
}